// round 16
// baseline (speedup 1.0000x reference)
#include <cuda_runtime.h>
#include <cuda_fp16.h>
#include <cstdint>

#define HID 2048
#define NH  16
#define DH  128
#define LAT 512
#define TT  2048
#define BT  4096
#define BH  32

typedef __half f16;

// ------------------------- static scratch ----------------------------------
__device__ __align__(256) f16 g_xh[(size_t)BT * HID];
__device__ __align__(256) f16 g_wqh[(size_t)HID * HID], g_wql[(size_t)HID * HID];
__device__ __align__(256) f16 g_wlh[(size_t)LAT * HID], g_wll[(size_t)LAT * HID];
__device__ __align__(256) f16 g_wkh[(size_t)HID * LAT], g_wkl[(size_t)HID * LAT];
__device__ __align__(256) f16 g_wvh[(size_t)HID * LAT], g_wvl[(size_t)HID * LAT];
__device__ __align__(256) f16 g_woh[(size_t)HID * HID], g_wol[(size_t)HID * HID];
__device__ __align__(256) f16 g_lath[(size_t)BT * LAT];
__device__ __align__(256) f16 g_qh[(size_t)BH * TT * DH];
__device__ __align__(256) f16 g_kh[(size_t)BH * TT * DH];
__device__ __align__(256) f16 g_vth[(size_t)BH * TT * DH];
__device__ __align__(256) f16 g_ath[(size_t)BT * HID];

// ------------------------- helpers ----------------------------------------
__device__ __forceinline__ uint32_t smem_u32(const void* p) {
    uint32_t a;
    asm("{ .reg .u64 t; cvta.to.shared.u64 t, %1; cvt.u32.u64 %0, t; }"
        : "=r"(a) : "l"(p));
    return a;
}
__device__ __forceinline__ float f16r(float x) {
    return __half2float(__float2half_rn(x));
}
__device__ __forceinline__ uint32_t pk2(float a, float b) {
    __half2 t = __floats2half2_rn(a, b);
    return *reinterpret_cast<uint32_t*>(&t);
}
__device__ __forceinline__ void cp16(uint32_t s, const void* g) {
    asm volatile("cp.async.cg.shared.global [%0], [%1], 16;" :: "r"(s), "l"(g));
}
__device__ __forceinline__ void mma16816(float* c, const uint32_t* a,
                                         const uint32_t* b) {
    asm volatile("mma.sync.aligned.m16n8k16.row.col.f32.f16.f16.f32 "
        "{%0,%1,%2,%3}, {%4,%5,%6,%7}, {%8,%9}, {%0,%1,%2,%3};"
        : "+f"(c[0]), "+f"(c[1]), "+f"(c[2]), "+f"(c[3])
        : "r"(a[0]), "r"(a[1]), "r"(a[2]), "r"(a[3]), "r"(b[0]), "r"(b[1]));
}
__device__ __forceinline__ void ldsm4(uint32_t* r, uint32_t addr) {
    asm volatile("ldmatrix.sync.aligned.m8n8.x4.shared.b16 {%0,%1,%2,%3}, [%4];"
        : "=r"(r[0]), "=r"(r[1]), "=r"(r[2]), "=r"(r[3]) : "r"(addr));
}

// ------------------------- fused prep --------------------------------------
__device__ __forceinline__ void trans_tile(const float* __restrict__ W,
                                           f16* __restrict__ OH,
                                           f16* __restrict__ OL,
                                           int K, int N, int n0, int k0,
                                           float tile[32][33],
                                           int tx, int ty) {
#pragma unroll
    for (int j = 0; j < 32; j += 8)
        tile[ty + j][tx] = W[(size_t)(k0 + ty + j) * N + n0 + tx];
    __syncthreads();
#pragma unroll
    for (int j = 0; j < 32; j += 8) {
        float v = tile[tx][ty + j];
        float h = f16r(v);
        size_t idx = (size_t)(n0 + ty + j) * K + k0 + tx;
        OH[idx] = __float2half_rn(h);
        OL[idx] = __float2half_rn(v - h);
    }
}

__global__ void prep_all(const float* __restrict__ X,
                         const float* __restrict__ Wq, const float* __restrict__ Wl,
                         const float* __restrict__ Wk, const float* __restrict__ Wv,
                         const float* __restrict__ Wo,
                         f16* xh,
                         f16* wqh, f16* wql, f16* wlh, f16* wll,
                         f16* wkh, f16* wkl, f16* wvh, f16* wvl,
                         f16* woh, f16* wol) {
    __shared__ float tile[32][33];
    int b = blockIdx.x;
    int tx = threadIdx.x, ty = threadIdx.y;
    if (b < 8192) {            // x -> fp16 (hi only)
        int i = b * 256 + ty * 32 + tx;
        float4 v = ((const float4*)X)[i];
        uint2 h;
        h.x = pk2(v.x, v.y); h.y = pk2(v.z, v.w);
        *(uint2*)(xh + (size_t)i * 4) = h;
        return;
    }
    b -= 8192;
    if (b < 4096) {
        trans_tile(Wq, wqh, wql, HID, HID, (b & 63) * 32, (b >> 6) * 32, tile, tx, ty);
    } else if (b < 5120) {
        b -= 4096;
        trans_tile(Wl, wlh, wll, HID, LAT, (b & 15) * 32, (b >> 4) * 32, tile, tx, ty);
    } else if (b < 6144) {
        b -= 5120;
        int h = b >> 6;
        trans_tile(Wk + (size_t)h * LAT * DH, wkh + (size_t)h * DH * LAT,
                   wkl + (size_t)h * DH * LAT, LAT, DH,
                   (b & 3) * 32, ((b >> 2) & 15) * 32, tile, tx, ty);
    } else if (b < 7168) {
        b -= 6144;
        int h = b >> 6;
        trans_tile(Wv + (size_t)h * LAT * DH, wvh + (size_t)h * DH * LAT,
                   wvl + (size_t)h * DH * LAT, LAT, DH,
                   (b & 3) * 32, ((b >> 2) & 15) * 32, tile, tx, ty);
    } else {
        b -= 7168;
        trans_tile(Wo, woh, wol, HID, HID, (b & 63) * 32, (b >> 6) * 32, tile, tx, ty);
    }
}

// ------------------------- fused HMMA GEMM ---------------------------------
// NB=2: C = alpha*(Ah@(Bh+Bl)^T + bias)  (weight hi/lo split)
// NB=1: C = alpha*(Ah@Bh^T + bias)       (plain fp16)
// cmode 0: fp32 out0[m*ldc+n]
//       1: fp16 hi-only plain oh[m*ldc+n]
//       3: hi-only scatter V^T -> [bh][d][t]
//       4: hi-only scatter -> [bh][t][d]
struct GP {
    const f16* Bh; const f16* Bl;
    const float* bias;
    float* out0; f16* oh; f16* ol;
    int nx; int cmode; int ldc; float alpha;
};

template<int NB>
__global__ void __launch_bounds__(256, 2)
mma_gemm2(const f16* __restrict__ Ah,
          int K, int lda, int ldb, GP p0, GP p1)
{
    extern __shared__ char smem[];
    const uint32_t sb = smem_u32(smem);
    const int tid = threadIdx.x, lid = tid & 31, wid = tid >> 5;
    const int wm = wid >> 1, wn = wid & 1;
    const uint32_t STG = (uint32_t)(1 + NB) * 10240u;

    int bx = blockIdx.x;
    const bool first = bx < p0.nx;
    if (!first) bx -= p0.nx;
    const f16* Bh = first ? p0.Bh : p1.Bh;
    const f16* Bl = first ? p0.Bl : p1.Bl;
    const float* bias = first ? p0.bias : p1.bias;
    float* out0 = first ? p0.out0 : p1.out0;
    f16* oh = first ? p0.oh : p1.oh;
    const int cm  = first ? p0.cmode : p1.cmode;
    const int ldc = first ? p0.ldc : p1.ldc;
    const float alpha = first ? p0.alpha : p1.alpha;

    const int row0 = blockIdx.y << 7, col0 = bx << 7;

    const f16* gsrc[1 + NB];
    gsrc[0] = Ah + (size_t)row0 * lda;
    gsrc[1] = Bh + (size_t)col0 * ldb;
    if (NB == 2) gsrc[2] = Bl + (size_t)col0 * ldb;

    const int nt = K >> 5;

    auto load_stage = [&](int buf, int kt) {
#pragma unroll
        for (int i = 0; i < 2 * (1 + NB); ++i) {
            int cid = tid + (i << 8);
            int q = cid >> 9, idx = cid & 511;
            int row = idx >> 2, c = idx & 3;
            int ld = (q == 0) ? lda : ldb;
            const f16* g = gsrc[q] + (size_t)row * ld + (kt << 5) + (c << 3);
            uint32_t s = sb + (uint32_t)buf * STG + (uint32_t)q * 10240u
                            + (uint32_t)row * 80u + ((uint32_t)c << 4);
            cp16(s, g);
        }
        asm volatile("cp.async.commit_group;" ::: "memory");
    };

    float acc[2][8][4];
#pragma unroll
    for (int mi = 0; mi < 2; ++mi)
#pragma unroll
        for (int nj = 0; nj < 8; ++nj)
#pragma unroll
            for (int p = 0; p < 4; ++p) acc[mi][nj][p] = 0.f;

    load_stage(0, 0);
    if (nt > 1) load_stage(1, 1);

    const int rowA = lid & 15;
    const int cA   = lid >> 4;
    const int rowB = (lid & 7) + ((lid >> 4) << 3);
    const int cB   = (lid >> 3) & 1;

    for (int t = 0; t < nt; ++t) {
        if (t + 1 < nt)
            asm volatile("cp.async.wait_group 1;" ::: "memory");
        else
            asm volatile("cp.async.wait_group 0;" ::: "memory");
        __syncthreads();
        const uint32_t st = sb + (uint32_t)(t & 1) * STG;

#pragma unroll
        for (int ks = 0; ks < 2; ++ks) {
            uint32_t a[2][4];
#pragma unroll
            for (int mi = 0; mi < 2; ++mi) {
                ldsm4(a[mi], st + (uint32_t)(wm * 32 + mi * 16 + rowA) * 80u
                           + (uint32_t)(ks * 2 + cA) * 16u);
            }
#pragma unroll
            for (int nj = 0; nj < 4; ++nj) {
                uint32_t bh2[4], bl2[4];
                uint32_t ab = st + 10240u
                    + (uint32_t)(wn * 64 + nj * 16 + rowB) * 80u
                    + (uint32_t)(ks * 2 + cB) * 16u;
                ldsm4(bh2, ab);
                if (NB == 2) ldsm4(bl2, ab + 10240u);
#pragma unroll
                for (int mi = 0; mi < 2; ++mi)
#pragma unroll
                    for (int p = 0; p < 2; ++p) {
                        float* c = acc[mi][nj * 2 + p];
                        mma16816(c, a[mi], bh2 + 2 * p);
                        if (NB == 2) mma16816(c, a[mi], bl2 + 2 * p);
                    }
            }
        }
        __syncthreads();
        if (t + 2 < nt) load_stage(t & 1, t + 2);
    }

    const int g = lid >> 2, tig = lid & 3;
#pragma unroll
    for (int mi = 0; mi < 2; ++mi)
#pragma unroll
    for (int hh = 0; hh < 2; ++hh) {
        const int m = row0 + wm * 32 + mi * 16 + g + hh * 8;
#pragma unroll
        for (int nj = 0; nj < 8; ++nj) {
            const int n = col0 + wn * 64 + nj * 8 + tig * 2;
            float v0 = acc[mi][nj][hh * 2 + 0];
            float v1 = acc[mi][nj][hh * 2 + 1];
            if (bias) { v0 += bias[n]; v1 += bias[n + 1]; }
            v0 *= alpha; v1 *= alpha;
            if (cm == 0) {
                *(float2*)(out0 + (size_t)m * ldc + n) = make_float2(v0, v1);
            } else if (cm == 1) {
                *(uint32_t*)(oh + (size_t)m * ldc + n) = pk2(v0, v1);
            } else if (cm == 3) {
                int b = m >> 11, t2 = m & (TT - 1);
                size_t i0 = ((size_t)((b << 4) + (n >> 7)) * DH + (n & 127)) * TT + t2;
                oh[i0]      = __float2half_rn(v0);
                oh[i0 + TT] = __float2half_rn(v1);
            } else { // 4
                int b = m >> 11, t2 = m & (TT - 1);
                size_t base = ((size_t)((b << 4) + (n >> 7)) * TT + t2) * DH + (n & 127);
                *(uint32_t*)(oh + base) = pk2(v0, v1);
            }
        }
    }
}

// ------------------------- fused flash attention ---------------------------
// S = Qh@Kh^T (single MMA); P single fp16; O += P@V; output fp16 hi only.
#define BKV  64
#define NCH  (TT / BKV)
#define KROW 272u
#define VROW 144u
#define VOFF  17408u
#define STSTR 35840u

__global__ void __launch_bounds__(256, 1)
flash_attn(const f16* __restrict__ Qh,
           const f16* __restrict__ Kh, const f16* __restrict__ Vt,
           f16* __restrict__ oh)
{
    extern __shared__ char smem[];
    const uint32_t sb = smem_u32(smem);
    const int tid = threadIdx.x, lid = tid & 31, wid = tid >> 5;
    const int bh = blockIdx.y;
    const int q0 = blockIdx.x << 7;

    const f16* qhb = Qh + ((size_t)bh * TT + q0) * DH;
    const f16* khb = Kh + (size_t)bh * TT * DH;
    const f16* vtb = Vt + (size_t)bh * DH * TT;

    // ---- stage Q hi (2048 16B chunks) ----
#pragma unroll
    for (int j = 0; j < 8; ++j) {
        int cid = tid + (j << 8);
        int row = cid >> 4, c = cid & 15;
        cp16(sb + (uint32_t)row * KROW + ((uint32_t)c << 4),
             qhb + (size_t)row * DH + (c << 3));
    }
    asm volatile("cp.async.commit_group;" ::: "memory");
    asm volatile("cp.async.wait_group 0;" ::: "memory");
    __syncthreads();

    const int rowA = lid & 15, cA = lid >> 4;
    const int rowB = (lid & 7) + ((lid >> 4) << 3), cB = (lid >> 3) & 1;

    uint32_t qfh[8][4];
#pragma unroll
    for (int kd = 0; kd < 8; ++kd) {
        ldsm4(qfh[kd], sb + (uint32_t)(wid * 16 + rowA) * KROW
                          + (uint32_t)(kd * 32 + cA * 16));
    }
    __syncthreads();

    auto load_kv = [&](int buf, int i) {
        uint32_t s0 = sb + (uint32_t)buf * STSTR;
#pragma unroll
        for (int j = 0; j < 4; ++j) {
            int cid = tid + (j << 8);
            int row = cid >> 4, c = cid & 15;
            cp16(s0 + (uint32_t)row * KROW + ((uint32_t)c << 4),
                 khb + (size_t)(i * BKV + row) * DH + (c << 3));
        }
#pragma unroll
        for (int j = 0; j < 4; ++j) {
            int cid = tid + (j << 8);
            int row = cid >> 3, c = cid & 7;
            cp16(s0 + VOFF + (uint32_t)row * VROW + ((uint32_t)c << 4),
                 vtb + (size_t)row * TT + i * BKV + (c << 3));
        }
        asm volatile("cp.async.commit_group;" ::: "memory");
    };

    float o[16][4];
#pragma unroll
    for (int dj = 0; dj < 16; ++dj)
#pragma unroll
        for (int p = 0; p < 4; ++p) o[dj][p] = 0.f;
    float m0 = -1e30f, m1 = -1e30f, l0 = 0.f, l1 = 0.f;

    load_kv(0, 0);
    load_kv(1, 1);

    for (int i = 0; i < NCH; ++i) {
        if (i + 1 < NCH) asm volatile("cp.async.wait_group 1;" ::: "memory");
        else             asm volatile("cp.async.wait_group 0;" ::: "memory");
        __syncthreads();
        if (i + 2 < NCH) load_kv((i + 2) % 3, i + 2);
        const uint32_t st = sb + (uint32_t)(i % 3) * STSTR;

        // ---- S = Qh @ Kh^T ----
        float s[8][4];
#pragma unroll
        for (int nj = 0; nj < 8; ++nj)
#pragma unroll
            for (int p = 0; p < 4; ++p) s[nj][p] = 0.f;
#pragma unroll
        for (int kd = 0; kd < 8; ++kd) {
#pragma unroll
            for (int g2 = 0; g2 < 4; ++g2) {
                uint32_t kf[4];
                ldsm4(kf, st + (uint32_t)(g2 * 16 + rowB) * KROW
                            + (uint32_t)(kd * 32 + cB * 16));
#pragma unroll
                for (int p = 0; p < 2; ++p)
                    mma16816(s[g2 * 2 + p], qfh[kd], kf + 2 * p);
            }
        }

        // ---- online softmax ----
        float mx0 = s[0][0], mx1 = s[0][2];
#pragma unroll
        for (int nj = 0; nj < 8; ++nj) {
            mx0 = fmaxf(mx0, fmaxf(s[nj][0], s[nj][1]));
            mx1 = fmaxf(mx1, fmaxf(s[nj][2], s[nj][3]));
        }
        mx0 = fmaxf(mx0, __shfl_xor_sync(~0u, mx0, 1));
        mx0 = fmaxf(mx0, __shfl_xor_sync(~0u, mx0, 2));
        mx1 = fmaxf(mx1, __shfl_xor_sync(~0u, mx1, 1));
        mx1 = fmaxf(mx1, __shfl_xor_sync(~0u, mx1, 2));
        float mn0 = fmaxf(m0, mx0), mn1 = fmaxf(m1, mx1);
        float es0 = __expf(m0 - mn0), es1 = __expf(m1 - mn1);
        m0 = mn0; m1 = mn1;
        l0 *= es0; l1 *= es1;
#pragma unroll
        for (int dj = 0; dj < 16; ++dj) {
            o[dj][0] *= es0; o[dj][1] *= es0;
            o[dj][2] *= es1; o[dj][3] *= es1;
        }
        float sum0 = 0.f, sum1 = 0.f;
#pragma unroll
        for (int nj = 0; nj < 8; ++nj) {
            s[nj][0] = __expf(s[nj][0] - m0);
            s[nj][1] = __expf(s[nj][1] - m0);
            s[nj][2] = __expf(s[nj][2] - m1);
            s[nj][3] = __expf(s[nj][3] - m1);
            sum0 += s[nj][0] + s[nj][1];
            sum1 += s[nj][2] + s[nj][3];
        }
        sum0 += __shfl_xor_sync(~0u, sum0, 1);
        sum0 += __shfl_xor_sync(~0u, sum0, 2);
        sum1 += __shfl_xor_sync(~0u, sum1, 1);
        sum1 += __shfl_xor_sync(~0u, sum1, 2);
        l0 += sum0; l1 += sum1;

        // ---- pack P ----
        uint32_t ap[4][4];
#pragma unroll
        for (int kt = 0; kt < 4; ++kt) {
            ap[kt][0] = pk2(s[2 * kt][0],     s[2 * kt][1]);
            ap[kt][1] = pk2(s[2 * kt][2],     s[2 * kt][3]);
            ap[kt][2] = pk2(s[2 * kt + 1][0], s[2 * kt + 1][1]);
            ap[kt][3] = pk2(s[2 * kt + 1][2], s[2 * kt + 1][3]);
        }

        // ---- O += P @ V ----
#pragma unroll
        for (int kt = 0; kt < 4; ++kt) {
#pragma unroll
            for (int dg = 0; dg < 8; ++dg) {
                uint32_t vf[4];
                ldsm4(vf, st + VOFF + (uint32_t)(dg * 16 + rowB) * VROW
                               + (uint32_t)(kt * 32 + cB * 16));
                mma16816(o[dg * 2 + 0], ap[kt], vf);
                mma16816(o[dg * 2 + 1], ap[kt], vf + 2);
            }
        }
    }

    // ---- epilogue: fp16 hi only ----
    float inv0 = 1.f / l0, inv1 = 1.f / l1;
    const int b = bh >> 4, h = bh & 15;
    const int g = lid >> 2, tig = lid & 3;
    const int mrow = q0 + wid * 16 + g;
#pragma unroll
    for (int dj = 0; dj < 16; ++dj) {
        int n = (h << 7) + dj * 8 + tig * 2;
        size_t b0 = (size_t)(b * TT + mrow) * HID + n;
        size_t b1 = (size_t)(b * TT + mrow + 8) * HID + n;
        *(uint32_t*)(oh + b0) = pk2(o[dj][0] * inv0, o[dj][1] * inv0);
        *(uint32_t*)(oh + b1) = pk2(o[dj][2] * inv1, o[dj][3] * inv1);
    }
}

// ------------------------- launcher ----------------------------------------
extern "C" void kernel_launch(void* const* d_in, const int* in_sizes, int n_in,
                              void* d_out, int out_size) {
    const float* x  = (const float*)d_in[0];
    const float* Wq = (const float*)d_in[1];
    const float* bq = (const float*)d_in[2];
    const float* Wl = (const float*)d_in[3];
    const float* bl = (const float*)d_in[4];
    const float* Wk = (const float*)d_in[5];
    const float* bk = (const float*)d_in[6];
    const float* Wv = (const float*)d_in[7];
    const float* bv = (const float*)d_in[8];
    const float* Wo = (const float*)d_in[9];
    const float* bo = (const float*)d_in[10];
    float* out = (float*)d_out;

    f16 *xh, *wqh, *wql, *wlh, *wll, *wkh, *wkl, *wvh, *wvl, *woh, *wol;
    f16 *lath, *qh, *kh, *vth, *ath;
    cudaGetSymbolAddress((void**)&xh, g_xh);
    cudaGetSymbolAddress((void**)&wqh, g_wqh); cudaGetSymbolAddress((void**)&wql, g_wql);
    cudaGetSymbolAddress((void**)&wlh, g_wlh); cudaGetSymbolAddress((void**)&wll, g_wll);
    cudaGetSymbolAddress((void**)&wkh, g_wkh); cudaGetSymbolAddress((void**)&wkl, g_wkl);
    cudaGetSymbolAddress((void**)&wvh, g_wvh); cudaGetSymbolAddress((void**)&wvl, g_wvl);
    cudaGetSymbolAddress((void**)&woh, g_woh); cudaGetSymbolAddress((void**)&wol, g_wol);
    cudaGetSymbolAddress((void**)&lath, g_lath);
    cudaGetSymbolAddress((void**)&qh, g_qh);
    cudaGetSymbolAddress((void**)&kh, g_kh);
    cudaGetSymbolAddress((void**)&vth, g_vth);
    cudaGetSymbolAddress((void**)&ath, g_ath);

    const int SMEM2 = 2 * 30720;  // NB=2
    const int SMEM1 = 2 * 20480;  // NB=1
    cudaFuncSetAttribute(mma_gemm2<2>, cudaFuncAttributeMaxDynamicSharedMemorySize, SMEM2);
    cudaFuncSetAttribute(mma_gemm2<1>, cudaFuncAttributeMaxDynamicSharedMemorySize, SMEM1);
    const int FSMEM = 3 * 35840;  // 107520
    cudaFuncSetAttribute(flash_attn, cudaFuncAttributeMaxDynamicSharedMemorySize, FSMEM);

    const float qscale = 0.08838834764831845f; // 1/sqrt(128)

    // launch 0: fused prep
    prep_all<<<19456, dim3(32, 8)>>>(x, Wq, Wl, Wk, Wv, Wo,
        xh, wqh, wql, wlh, wll, wkh, wkl, wvh, wvl, woh, wol);

    // launch 1: fused Q-proj (hi scatter) + latent (hi plain)
    {
        GP p0 = {wqh, wql, bq, nullptr, qh, nullptr, 16, 4, 0, qscale};
        GP p1 = {wlh, wll, bl, nullptr, lath, nullptr, 4, 1, LAT, 1.f};
        mma_gemm2<2><<<dim3(20, 32), 256, SMEM2>>>(xh, HID, HID, HID, p0, p1);
    }
    // launch 2: fused K-proj (hi scatter) + V-proj (hi V^T)
    {
        GP p0 = {wkh, wkl, bk, nullptr, kh, nullptr, 16, 4, 0, 1.f};
        GP p1 = {wvh, wvl, bv, nullptr, vth, nullptr, 16, 3, 0, 1.f};
        mma_gemm2<2><<<dim3(32, 32), 256, SMEM2>>>(lath, LAT, LAT, LAT, p0, p1);
    }
    // launch 3 (ncu-profiled slot): fused attention -> ath (fp16)
    flash_attn<<<dim3(TT / 128, BH), 256, FSMEM>>>(qh, kh, vth, ath);
    // launch 4: out = ath@Woh + bo (fp32 out, single-MMA)
    {
        GP p0 = {woh, nullptr, bo, out, nullptr, nullptr, 16, 0, HID, 1.f};
        mma_gemm2<1><<<dim3(16, 32), 256, SMEM1>>>(ath, HID, HID, HID, p0, p0);
    }
}

// round 17
// speedup vs baseline: 1.2709x; 1.2709x over previous
#include <cuda_runtime.h>
#include <cuda_fp16.h>
#include <cstdint>

#define HID 2048
#define NH  16
#define DH  128
#define LAT 512
#define TT  2048
#define BT  4096
#define BH  32

typedef __half f16;

// ------------------------- static scratch ----------------------------------
__device__ __align__(256) f16 g_xh[(size_t)BT * HID];
__device__ __align__(256) f16 g_wqh[(size_t)HID * HID], g_wql[(size_t)HID * HID];
__device__ __align__(256) f16 g_wlh[(size_t)LAT * HID], g_wll[(size_t)LAT * HID];
__device__ __align__(256) f16 g_wkh[(size_t)HID * LAT], g_wkl[(size_t)HID * LAT];
__device__ __align__(256) f16 g_wvh[(size_t)HID * LAT], g_wvl[(size_t)HID * LAT];
__device__ __align__(256) f16 g_woh[(size_t)HID * HID], g_wol[(size_t)HID * HID];
__device__ __align__(256) f16 g_lath[(size_t)BT * LAT];
__device__ __align__(256) f16 g_qh[(size_t)BH * TT * DH], g_ql[(size_t)BH * TT * DH];
__device__ __align__(256) f16 g_kh[(size_t)BH * TT * DH];
__device__ __align__(256) f16 g_vth[(size_t)BH * TT * DH];
__device__ __align__(256) f16 g_ath[(size_t)BT * HID];

// ------------------------- helpers ----------------------------------------
__device__ __forceinline__ uint32_t smem_u32(const void* p) {
    uint32_t a;
    asm("{ .reg .u64 t; cvta.to.shared.u64 t, %1; cvt.u32.u64 %0, t; }"
        : "=r"(a) : "l"(p));
    return a;
}
__device__ __forceinline__ float f16r(float x) {
    return __half2float(__float2half_rn(x));
}
__device__ __forceinline__ uint32_t pk2(float a, float b) {
    __half2 t = __floats2half2_rn(a, b);
    return *reinterpret_cast<uint32_t*>(&t);
}
__device__ __forceinline__ void cp16(uint32_t s, const void* g) {
    asm volatile("cp.async.cg.shared.global [%0], [%1], 16;" :: "r"(s), "l"(g));
}
__device__ __forceinline__ void mma16816(float* c, const uint32_t* a,
                                         const uint32_t* b) {
    asm volatile("mma.sync.aligned.m16n8k16.row.col.f32.f16.f16.f32 "
        "{%0,%1,%2,%3}, {%4,%5,%6,%7}, {%8,%9}, {%0,%1,%2,%3};"
        : "+f"(c[0]), "+f"(c[1]), "+f"(c[2]), "+f"(c[3])
        : "r"(a[0]), "r"(a[1]), "r"(a[2]), "r"(a[3]), "r"(b[0]), "r"(b[1]));
}
__device__ __forceinline__ void ldsm4(uint32_t* r, uint32_t addr) {
    asm volatile("ldmatrix.sync.aligned.m8n8.x4.shared.b16 {%0,%1,%2,%3}, [%4];"
        : "=r"(r[0]), "=r"(r[1]), "=r"(r[2]), "=r"(r[3]) : "r"(addr));
}

// ------------------------- fused prep --------------------------------------
__device__ __forceinline__ void trans_tile(const float* __restrict__ W,
                                           f16* __restrict__ OH,
                                           f16* __restrict__ OL,
                                           int K, int N, int n0, int k0,
                                           float tile[32][33],
                                           int tx, int ty) {
#pragma unroll
    for (int j = 0; j < 32; j += 8)
        tile[ty + j][tx] = W[(size_t)(k0 + ty + j) * N + n0 + tx];
    __syncthreads();
#pragma unroll
    for (int j = 0; j < 32; j += 8) {
        float v = tile[tx][ty + j];
        float h = f16r(v);
        size_t idx = (size_t)(n0 + ty + j) * K + k0 + tx;
        OH[idx] = __float2half_rn(h);
        OL[idx] = __float2half_rn(v - h);
    }
}

__global__ void prep_all(const float* __restrict__ X,
                         const float* __restrict__ Wq, const float* __restrict__ Wl,
                         const float* __restrict__ Wk, const float* __restrict__ Wv,
                         const float* __restrict__ Wo,
                         f16* xh,
                         f16* wqh, f16* wql, f16* wlh, f16* wll,
                         f16* wkh, f16* wkl, f16* wvh, f16* wvl,
                         f16* woh, f16* wol) {
    __shared__ float tile[32][33];
    int b = blockIdx.x;
    int tx = threadIdx.x, ty = threadIdx.y;
    if (b < 8192) {            // x -> fp16 (hi only)
        int i = b * 256 + ty * 32 + tx;
        float4 v = ((const float4*)X)[i];
        uint2 h;
        h.x = pk2(v.x, v.y); h.y = pk2(v.z, v.w);
        *(uint2*)(xh + (size_t)i * 4) = h;
        return;
    }
    b -= 8192;
    if (b < 4096) {
        trans_tile(Wq, wqh, wql, HID, HID, (b & 63) * 32, (b >> 6) * 32, tile, tx, ty);
    } else if (b < 5120) {
        b -= 4096;
        trans_tile(Wl, wlh, wll, HID, LAT, (b & 15) * 32, (b >> 4) * 32, tile, tx, ty);
    } else if (b < 6144) {
        b -= 5120;
        int h = b >> 6;
        trans_tile(Wk + (size_t)h * LAT * DH, wkh + (size_t)h * DH * LAT,
                   wkl + (size_t)h * DH * LAT, LAT, DH,
                   (b & 3) * 32, ((b >> 2) & 15) * 32, tile, tx, ty);
    } else if (b < 7168) {
        b -= 6144;
        int h = b >> 6;
        trans_tile(Wv + (size_t)h * LAT * DH, wvh + (size_t)h * DH * LAT,
                   wvl + (size_t)h * DH * LAT, LAT, DH,
                   (b & 3) * 32, ((b >> 2) & 15) * 32, tile, tx, ty);
    } else {
        b -= 7168;
        trans_tile(Wo, woh, wol, HID, HID, (b & 63) * 32, (b >> 6) * 32, tile, tx, ty);
    }
}

// ------------------------- fused HMMA GEMM ---------------------------------
// C(128x128) = alpha*(Ah@(Bh+Bl)^T + bias): 2-MMA split (activation rounded).
// cmode 0: fp32 out0[m*ldc+n]
//       1: fp16 hi-only plain oh[m*ldc+n]
//       2: split scatter both (oh,ol) -> [bh][t][d]   (Q)
//       3: hi-only scatter V^T -> [bh][d][t]          (V)
//       4: hi-only scatter -> [bh][t][d]              (K)
// 3 stages x 30720 B = 92160; single sync per k-tile; 2 CTAs/SM.
struct GP {
    const f16* Bh; const f16* Bl;
    const float* bias;
    float* out0; f16* oh; f16* ol;
    int nx; int cmode; int ldc; float alpha;
};

__global__ void __launch_bounds__(256, 2)
mma_gemm2(const f16* __restrict__ Ah,
          int K, int lda, int ldb, GP p0, GP p1)
{
    extern __shared__ char smem[];
    const uint32_t sb = smem_u32(smem);
    const int tid = threadIdx.x, lid = tid & 31, wid = tid >> 5;
    const int wm = wid >> 1, wn = wid & 1;

    int bx = blockIdx.x;
    const bool first = bx < p0.nx;
    if (!first) bx -= p0.nx;
    const f16* Bh = first ? p0.Bh : p1.Bh;
    const f16* Bl = first ? p0.Bl : p1.Bl;
    const float* bias = first ? p0.bias : p1.bias;
    float* out0 = first ? p0.out0 : p1.out0;
    f16* oh = first ? p0.oh : p1.oh;
    f16* ol = first ? p0.ol : p1.ol;
    const int cm  = first ? p0.cmode : p1.cmode;
    const int ldc = first ? p0.ldc : p1.ldc;
    const float alpha = first ? p0.alpha : p1.alpha;

    const int row0 = blockIdx.y << 7, col0 = bx << 7;

    const f16* gsrc[3];
    gsrc[0] = Ah + (size_t)row0 * lda;
    gsrc[1] = Bh + (size_t)col0 * ldb;
    gsrc[2] = Bl + (size_t)col0 * ldb;

    const int nt = K >> 5;

    // 1536 16B-chunks per stage, 6 per thread
    auto load_stage = [&](int buf, int kt) {
#pragma unroll
        for (int i = 0; i < 6; ++i) {
            int cid = tid + (i << 8);
            int q = cid >> 9, idx = cid & 511;
            int row = idx >> 2, c = idx & 3;
            int ld = (q == 0) ? lda : ldb;
            const f16* g = gsrc[q] + (size_t)row * ld + (kt << 5) + (c << 3);
            uint32_t s = sb + (uint32_t)(buf * 3 + q) * 10240u
                            + (uint32_t)row * 80u + ((uint32_t)c << 4);
            cp16(s, g);
        }
        asm volatile("cp.async.commit_group;" ::: "memory");
    };

    float acc[2][8][4];
#pragma unroll
    for (int mi = 0; mi < 2; ++mi)
#pragma unroll
        for (int nj = 0; nj < 8; ++nj)
#pragma unroll
            for (int p = 0; p < 4; ++p) acc[mi][nj][p] = 0.f;

    load_stage(0, 0);
    if (nt > 1) load_stage(1, 1);

    const int rowA = lid & 15;
    const int cA   = lid >> 4;
    const int rowB = (lid & 7) + ((lid >> 4) << 3);
    const int cB   = (lid >> 3) & 1;

    for (int t = 0; t < nt; ++t) {
        if (t + 1 < nt)
            asm volatile("cp.async.wait_group 1;" ::: "memory");
        else
            asm volatile("cp.async.wait_group 0;" ::: "memory");
        __syncthreads();   // protects buf t%3; proves buf (t+2)%3 (from t-1) free
        if (t + 2 < nt) load_stage((t + 2) % 3, t + 2);
        const uint32_t st = sb + (uint32_t)(t % 3) * 30720u;

#pragma unroll
        for (int ks = 0; ks < 2; ++ks) {
            uint32_t a[2][4];
#pragma unroll
            for (int mi = 0; mi < 2; ++mi) {
                ldsm4(a[mi], st + (uint32_t)(wm * 32 + mi * 16 + rowA) * 80u
                           + (uint32_t)(ks * 2 + cA) * 16u);
            }
#pragma unroll
            for (int nj = 0; nj < 4; ++nj) {
                uint32_t bh2[4], bl2[4];
                uint32_t ab = st + 10240u
                    + (uint32_t)(wn * 64 + nj * 16 + rowB) * 80u
                    + (uint32_t)(ks * 2 + cB) * 16u;
                ldsm4(bh2, ab);
                ldsm4(bl2, ab + 10240u);
#pragma unroll
                for (int mi = 0; mi < 2; ++mi)
#pragma unroll
                    for (int p = 0; p < 2; ++p) {
                        float* c = acc[mi][nj * 2 + p];
                        mma16816(c, a[mi], bh2 + 2 * p);
                        mma16816(c, a[mi], bl2 + 2 * p);
                    }
            }
        }
        // no trailing sync: next iteration's barrier protects buffer reuse
    }

    const int g = lid >> 2, tig = lid & 3;
#pragma unroll
    for (int mi = 0; mi < 2; ++mi)
#pragma unroll
    for (int hh = 0; hh < 2; ++hh) {
        const int m = row0 + wm * 32 + mi * 16 + g + hh * 8;
#pragma unroll
        for (int nj = 0; nj < 8; ++nj) {
            const int n = col0 + wn * 64 + nj * 8 + tig * 2;
            float v0 = acc[mi][nj][hh * 2 + 0];
            float v1 = acc[mi][nj][hh * 2 + 1];
            if (bias) { v0 += bias[n]; v1 += bias[n + 1]; }
            v0 *= alpha; v1 *= alpha;
            if (cm == 0) {
                *(float2*)(out0 + (size_t)m * ldc + n) = make_float2(v0, v1);
            } else if (cm == 1) {
                *(uint32_t*)(oh + (size_t)m * ldc + n) = pk2(v0, v1);
            } else if (cm == 2) {
                int b = m >> 11, t2 = m & (TT - 1);
                size_t base = ((size_t)((b << 4) + (n >> 7)) * TT + t2) * DH + (n & 127);
                float h0 = f16r(v0), h1 = f16r(v1);
                *(uint32_t*)(oh + base) = pk2(h0, h1);
                *(uint32_t*)(ol + base) = pk2(v0 - h0, v1 - h1);
            } else if (cm == 3) {
                int b = m >> 11, t2 = m & (TT - 1);
                size_t i0 = ((size_t)((b << 4) + (n >> 7)) * DH + (n & 127)) * TT + t2;
                oh[i0]      = __float2half_rn(v0);
                oh[i0 + TT] = __float2half_rn(v1);
            } else { // 4
                int b = m >> 11, t2 = m & (TT - 1);
                size_t base = ((size_t)((b << 4) + (n >> 7)) * TT + t2) * DH + (n & 127);
                *(uint32_t*)(oh + base) = pk2(v0, v1);
            }
        }
    }
}

// ------------------------- fused flash attention ---------------------------
// S = (Qh+Ql)@Kh^T (2-MMA); P single fp16; O += P@V; output fp16 hi only.
#define BKV  64
#define NCH  (TT / BKV)
#define KROW 272u
#define VROW 144u
#define VOFF  17408u
#define STSTR 35840u

__global__ void __launch_bounds__(256, 1)
flash_attn(const f16* __restrict__ Qh, const f16* __restrict__ Ql,
           const f16* __restrict__ Kh, const f16* __restrict__ Vt,
           f16* __restrict__ oh)
{
    extern __shared__ char smem[];
    const uint32_t sb = smem_u32(smem);
    const int tid = threadIdx.x, lid = tid & 31, wid = tid >> 5;
    const int bh = blockIdx.y;
    const int q0 = blockIdx.x << 7;

    const f16* qhb = Qh + ((size_t)bh * TT + q0) * DH;
    const f16* qlb = Ql + ((size_t)bh * TT + q0) * DH;
    const f16* khb = Kh + (size_t)bh * TT * DH;
    const f16* vtb = Vt + (size_t)bh * DH * TT;

#pragma unroll
    for (int j = 0; j < 8; ++j) {
        int cid = tid + (j << 8);
        int row = cid >> 4, c = cid & 15;
        cp16(sb + (uint32_t)row * KROW + ((uint32_t)c << 4),
             qhb + (size_t)row * DH + (c << 3));
        cp16(sb + STSTR + (uint32_t)row * KROW + ((uint32_t)c << 4),
             qlb + (size_t)row * DH + (c << 3));
    }
    asm volatile("cp.async.commit_group;" ::: "memory");
    asm volatile("cp.async.wait_group 0;" ::: "memory");
    __syncthreads();

    const int rowA = lid & 15, cA = lid >> 4;
    const int rowB = (lid & 7) + ((lid >> 4) << 3), cB = (lid >> 3) & 1;

    uint32_t qfh[8][4], qfl[8][4];
#pragma unroll
    for (int kd = 0; kd < 8; ++kd) {
        uint32_t addr = sb + (uint32_t)(wid * 16 + rowA) * KROW
                           + (uint32_t)(kd * 32 + cA * 16);
        ldsm4(qfh[kd], addr);
        ldsm4(qfl[kd], addr + STSTR);
    }
    __syncthreads();

    auto load_kv = [&](int buf, int i) {
        uint32_t s0 = sb + (uint32_t)buf * STSTR;
#pragma unroll
        for (int j = 0; j < 4; ++j) {
            int cid = tid + (j << 8);
            int row = cid >> 4, c = cid & 15;
            cp16(s0 + (uint32_t)row * KROW + ((uint32_t)c << 4),
                 khb + (size_t)(i * BKV + row) * DH + (c << 3));
        }
#pragma unroll
        for (int j = 0; j < 4; ++j) {
            int cid = tid + (j << 8);
            int row = cid >> 3, c = cid & 7;
            cp16(s0 + VOFF + (uint32_t)row * VROW + ((uint32_t)c << 4),
                 vtb + (size_t)row * TT + i * BKV + (c << 3));
        }
        asm volatile("cp.async.commit_group;" ::: "memory");
    };

    float o[16][4];
#pragma unroll
    for (int dj = 0; dj < 16; ++dj)
#pragma unroll
        for (int p = 0; p < 4; ++p) o[dj][p] = 0.f;
    float m0 = -1e30f, m1 = -1e30f, l0 = 0.f, l1 = 0.f;

    load_kv(0, 0);
    load_kv(1, 1);

    for (int i = 0; i < NCH; ++i) {
        if (i + 1 < NCH) asm volatile("cp.async.wait_group 1;" ::: "memory");
        else             asm volatile("cp.async.wait_group 0;" ::: "memory");
        __syncthreads();
        if (i + 2 < NCH) load_kv((i + 2) % 3, i + 2);
        const uint32_t st = sb + (uint32_t)(i % 3) * STSTR;

        // ---- S = (Qh+Ql) @ Kh^T (2-MMA split) ----
        float s[8][4];
#pragma unroll
        for (int nj = 0; nj < 8; ++nj)
#pragma unroll
            for (int p = 0; p < 4; ++p) s[nj][p] = 0.f;
#pragma unroll
        for (int kd = 0; kd < 8; ++kd) {
#pragma unroll
            for (int g2 = 0; g2 < 4; ++g2) {
                uint32_t kf[4];
                ldsm4(kf, st + (uint32_t)(g2 * 16 + rowB) * KROW
                            + (uint32_t)(kd * 32 + cB * 16));
#pragma unroll
                for (int p = 0; p < 2; ++p) {
                    float* c = s[g2 * 2 + p];
                    mma16816(c, qfh[kd], kf + 2 * p);
                    mma16816(c, qfl[kd], kf + 2 * p);
                }
            }
        }

        // ---- online softmax ----
        float mx0 = s[0][0], mx1 = s[0][2];
#pragma unroll
        for (int nj = 0; nj < 8; ++nj) {
            mx0 = fmaxf(mx0, fmaxf(s[nj][0], s[nj][1]));
            mx1 = fmaxf(mx1, fmaxf(s[nj][2], s[nj][3]));
        }
        mx0 = fmaxf(mx0, __shfl_xor_sync(~0u, mx0, 1));
        mx0 = fmaxf(mx0, __shfl_xor_sync(~0u, mx0, 2));
        mx1 = fmaxf(mx1, __shfl_xor_sync(~0u, mx1, 1));
        mx1 = fmaxf(mx1, __shfl_xor_sync(~0u, mx1, 2));
        float mn0 = fmaxf(m0, mx0), mn1 = fmaxf(m1, mx1);
        float es0 = __expf(m0 - mn0), es1 = __expf(m1 - mn1);
        m0 = mn0; m1 = mn1;
        l0 *= es0; l1 *= es1;
#pragma unroll
        for (int dj = 0; dj < 16; ++dj) {
            o[dj][0] *= es0; o[dj][1] *= es0;
            o[dj][2] *= es1; o[dj][3] *= es1;
        }
        float sum0 = 0.f, sum1 = 0.f;
#pragma unroll
        for (int nj = 0; nj < 8; ++nj) {
            s[nj][0] = __expf(s[nj][0] - m0);
            s[nj][1] = __expf(s[nj][1] - m0);
            s[nj][2] = __expf(s[nj][2] - m1);
            s[nj][3] = __expf(s[nj][3] - m1);
            sum0 += s[nj][0] + s[nj][1];
            sum1 += s[nj][2] + s[nj][3];
        }
        sum0 += __shfl_xor_sync(~0u, sum0, 1);
        sum0 += __shfl_xor_sync(~0u, sum0, 2);
        sum1 += __shfl_xor_sync(~0u, sum1, 1);
        sum1 += __shfl_xor_sync(~0u, sum1, 2);
        l0 += sum0; l1 += sum1;

        // ---- pack P ----
        uint32_t ap[4][4];
#pragma unroll
        for (int kt = 0; kt < 4; ++kt) {
            ap[kt][0] = pk2(s[2 * kt][0],     s[2 * kt][1]);
            ap[kt][1] = pk2(s[2 * kt][2],     s[2 * kt][3]);
            ap[kt][2] = pk2(s[2 * kt + 1][0], s[2 * kt + 1][1]);
            ap[kt][3] = pk2(s[2 * kt + 1][2], s[2 * kt + 1][3]);
        }

        // ---- O += P @ V ----
#pragma unroll
        for (int kt = 0; kt < 4; ++kt) {
#pragma unroll
            for (int dg = 0; dg < 8; ++dg) {
                uint32_t vf[4];
                ldsm4(vf, st + VOFF + (uint32_t)(dg * 16 + rowB) * VROW
                               + (uint32_t)(kt * 32 + cB * 16));
                mma16816(o[dg * 2 + 0], ap[kt], vf);
                mma16816(o[dg * 2 + 1], ap[kt], vf + 2);
            }
        }
    }

    // ---- epilogue: fp16 hi only ----
    float inv0 = 1.f / l0, inv1 = 1.f / l1;
    const int b = bh >> 4, h = bh & 15;
    const int g = lid >> 2, tig = lid & 3;
    const int mrow = q0 + wid * 16 + g;
#pragma unroll
    for (int dj = 0; dj < 16; ++dj) {
        int n = (h << 7) + dj * 8 + tig * 2;
        size_t b0 = (size_t)(b * TT + mrow) * HID + n;
        size_t b1 = (size_t)(b * TT + mrow + 8) * HID + n;
        *(uint32_t*)(oh + b0) = pk2(o[dj][0] * inv0, o[dj][1] * inv0);
        *(uint32_t*)(oh + b1) = pk2(o[dj][2] * inv1, o[dj][3] * inv1);
    }
}

// ------------------------- launcher ----------------------------------------
extern "C" void kernel_launch(void* const* d_in, const int* in_sizes, int n_in,
                              void* d_out, int out_size) {
    const float* x  = (const float*)d_in[0];
    const float* Wq = (const float*)d_in[1];
    const float* bq = (const float*)d_in[2];
    const float* Wl = (const float*)d_in[3];
    const float* bl = (const float*)d_in[4];
    const float* Wk = (const float*)d_in[5];
    const float* bk = (const float*)d_in[6];
    const float* Wv = (const float*)d_in[7];
    const float* bv = (const float*)d_in[8];
    const float* Wo = (const float*)d_in[9];
    const float* bo = (const float*)d_in[10];
    float* out = (float*)d_out;

    f16 *xh, *wqh, *wql, *wlh, *wll, *wkh, *wkl, *wvh, *wvl, *woh, *wol;
    f16 *lath, *qh, *ql, *kh, *vth, *ath;
    cudaGetSymbolAddress((void**)&xh, g_xh);
    cudaGetSymbolAddress((void**)&wqh, g_wqh); cudaGetSymbolAddress((void**)&wql, g_wql);
    cudaGetSymbolAddress((void**)&wlh, g_wlh); cudaGetSymbolAddress((void**)&wll, g_wll);
    cudaGetSymbolAddress((void**)&wkh, g_wkh); cudaGetSymbolAddress((void**)&wkl, g_wkl);
    cudaGetSymbolAddress((void**)&wvh, g_wvh); cudaGetSymbolAddress((void**)&wvl, g_wvl);
    cudaGetSymbolAddress((void**)&woh, g_woh); cudaGetSymbolAddress((void**)&wol, g_wol);
    cudaGetSymbolAddress((void**)&lath, g_lath);
    cudaGetSymbolAddress((void**)&qh, g_qh);   cudaGetSymbolAddress((void**)&ql, g_ql);
    cudaGetSymbolAddress((void**)&kh, g_kh);
    cudaGetSymbolAddress((void**)&vth, g_vth);
    cudaGetSymbolAddress((void**)&ath, g_ath);

    const int SMEM = 3 * 30720;   // 92160 -> still 2 CTAs/SM
    cudaFuncSetAttribute(mma_gemm2, cudaFuncAttributeMaxDynamicSharedMemorySize, SMEM);
    const int FSMEM = 3 * 35840;  // 107520
    cudaFuncSetAttribute(flash_attn, cudaFuncAttributeMaxDynamicSharedMemorySize, FSMEM);

    const float qscale = 0.08838834764831845f; // 1/sqrt(128)

    // launch 0: fused prep (x->fp16 + all weight transposes)
    prep_all<<<19456, dim3(32, 8)>>>(x, Wq, Wl, Wk, Wv, Wo,
        xh, wqh, wql, wlh, wll, wkh, wkl, wvh, wvl, woh, wol);

    // launch 1: fused Q-proj (512 CTAs, split out) + latent (128 CTAs, hi out)
    {
        GP p0 = {wqh, wql, bq, nullptr, qh, ql, 16, 2, 0, qscale};
        GP p1 = {wlh, wll, bl, nullptr, lath, nullptr, 4, 1, LAT, 1.f};
        mma_gemm2<<<dim3(20, 32), 256, SMEM>>>(xh, HID, HID, HID, p0, p1);
    }
    // launch 2: fused K-proj (hi scatter) + V-proj (hi V^T)
    {
        GP p0 = {wkh, wkl, bk, nullptr, kh, nullptr, 16, 4, 0, 1.f};
        GP p1 = {wvh, wvl, bv, nullptr, vth, nullptr, 16, 3, 0, 1.f};
        mma_gemm2<<<dim3(32, 32), 256, SMEM>>>(lath, LAT, LAT, LAT, p0, p1);
    }
    // launch 3 (ncu-profiled slot): fused attention -> ath (fp16)
    flash_attn<<<dim3(TT / 128, BH), 256, FSMEM>>>(qh, ql, kh, vth, ath);
    // launch 4: out = ath@(Woh+Wol) + bo (fp32 out)
    {
        GP p0 = {woh, wol, bo, out, nullptr, nullptr, 16, 0, HID, 1.f};
        mma_gemm2<<<dim3(16, 32), 256, SMEM>>>(ath, HID, HID, HID, p0, p0);
    }
}